// round 10
// baseline (speedup 1.0000x reference)
#include <cuda_runtime.h>

#define B_  4
#define C_  64
#define K_  32
#define N_  131072           // D*H*W
#define XS  260              // X tile row stride (words)
#define LS  260              // L/A tile row stride (words)
#define CWS 36               // transposed codeword stride
#define E_ELEMS (B_*K_*C_)   // 8192

__device__ float g_asum[B_*K_];

typedef unsigned long long u64;

__device__ __forceinline__ u64 ffma2(u64 a, u64 b, u64 c) {
    u64 d; asm("fma.rn.f32x2 %0, %1, %2, %3;" : "=l"(d) : "l"(a), "l"(b), "l"(c));
    return d;
}
__device__ __forceinline__ u64 fadd2(u64 a, u64 b) {
    u64 d; asm("add.rn.f32x2 %0, %1, %2;" : "=l"(d) : "l"(a), "l"(b));
    return d;
}
__device__ __forceinline__ u64 pack2(float lo, float hi) {
    u64 d; asm("mov.b64 %0, {%1, %2};" : "=l"(d) : "f"(lo), "f"(hi));
    return d;
}
__device__ __forceinline__ float2 unpack2(u64 v) {
    float2 r; asm("mov.b64 {%0, %1}, %2;" : "=f"(r.x), "=f"(r.y) : "l"(v));
    return r;
}

// ---------------------------------------------------------------------------
__global__ void enc_init(float* __restrict__ out) {
    int i = blockIdx.x * 256 + threadIdx.x;
    if (i < E_ELEMS) out[i] = 0.0f;
    if (i < B_*K_)   g_asum[i] = 0.0f;
}

// ---------------------------------------------------------------------------
__global__ __launch_bounds__(256, 2) void enc_main(
    const float* __restrict__ X,    // (B, C, N)
    const float* __restrict__ cwg,  // (K, C)
    const float* __restrict__ sclg, // (K,)
    float* __restrict__ out)        // [E | coefA]
{
    extern __shared__ float sm[];
    float* Xs  = sm;                  // 64*260  X tile, [c][n] linear
    float* Lb  = Xs + 64*XS;          // 32*260  logits -> A, [k][n] linear
    float* cwt = Lb + 32*LS;          // 64*36   codewords^T
    float* x2s = cwt + 64*CWS;        // 256
    float* scl = x2s + 256;           // 32
    float* c4  = scl + 32;            // 32*4  (scl, -2*scl, scl*c2, 0)

    const int tid = threadIdx.x;
    const int b   = blockIdx.x >> 9;
    const int n0  = (blockIdx.x & 511) << 8;

    // ---- stage X tile (vectorized, coalesced, linear layout) ----
    const float* Xb = X + (size_t)b * C_ * N_ + n0;
    #pragma unroll
    for (int i = 0; i < 16; ++i) {
        int f = i * 256 + tid;
        int c = f >> 6, q = f & 63;
        float4 v = *(const float4*)(Xb + (size_t)c * N_ + q * 4);
        *(float4*)(Xs + c * XS + q * 4) = v;
    }
    // ---- stage codewords transposed [c][k] ----
    #pragma unroll
    for (int i = 0; i < 8; ++i) {
        int f = i * 256 + tid;        // f = k*64 + c
        cwt[(f & 63) * CWS + (f >> 6)] = cwg[f];
    }
    if (tid < K_) scl[tid] = sclg[tid];
    __syncthreads();

    if (tid < K_) {
        float s = 0.f;
        #pragma unroll
        for (int c = 0; c < C_; ++c) { float w = cwt[c*CWS + tid]; s = fmaf(w, w, s); }
        float sc = scl[tid];
        float4 v; v.x = sc; v.y = -2.f * sc; v.z = sc * s; v.w = 0.f;
        *(float4*)(c4 + tid * 4) = v;
    }

    // ---- Phase 1: logits GEMM, 8k x 8n per thread, 128 active threads ----
    if (tid < 128) {
        const int kq = tid & 3;              // k-octet 0..3
        const int k0 = kq * 8;
        const int nt = (tid >> 2) * 8;       // n base, 32 groups of 8
        u64 acc[4][8];                       // [npair][k]
        u64 x2a[4];
        #pragma unroll
        for (int i = 0; i < 4; ++i) {
            x2a[i] = 0ull;
            #pragma unroll
            for (int j = 0; j < 8; ++j) acc[i][j] = 0ull;
        }

        #pragma unroll 4
        for (int c = 0; c < 64; ++c) {
            ulonglong2 xa = *(const ulonglong2*)(Xs + c * XS + nt);
            ulonglong2 xb = *(const ulonglong2*)(Xs + c * XS + nt + 4);
            float4 wA = *(const float4*)(cwt + c * CWS + k0);
            float4 wB = *(const float4*)(cwt + c * CWS + k0 + 4);
            u64 w0 = pack2(wA.x, wA.x), w1 = pack2(wA.y, wA.y);
            u64 w2 = pack2(wA.z, wA.z), w3 = pack2(wA.w, wA.w);
            u64 w4 = pack2(wB.x, wB.x), w5 = pack2(wB.y, wB.y);
            u64 w6 = pack2(wB.z, wB.z), w7 = pack2(wB.w, wB.w);
            acc[0][0] = ffma2(xa.x, w0, acc[0][0]);
            acc[0][1] = ffma2(xa.x, w1, acc[0][1]);
            acc[0][2] = ffma2(xa.x, w2, acc[0][2]);
            acc[0][3] = ffma2(xa.x, w3, acc[0][3]);
            acc[0][4] = ffma2(xa.x, w4, acc[0][4]);
            acc[0][5] = ffma2(xa.x, w5, acc[0][5]);
            acc[0][6] = ffma2(xa.x, w6, acc[0][6]);
            acc[0][7] = ffma2(xa.x, w7, acc[0][7]);
            acc[1][0] = ffma2(xa.y, w0, acc[1][0]);
            acc[1][1] = ffma2(xa.y, w1, acc[1][1]);
            acc[1][2] = ffma2(xa.y, w2, acc[1][2]);
            acc[1][3] = ffma2(xa.y, w3, acc[1][3]);
            acc[1][4] = ffma2(xa.y, w4, acc[1][4]);
            acc[1][5] = ffma2(xa.y, w5, acc[1][5]);
            acc[1][6] = ffma2(xa.y, w6, acc[1][6]);
            acc[1][7] = ffma2(xa.y, w7, acc[1][7]);
            acc[2][0] = ffma2(xb.x, w0, acc[2][0]);
            acc[2][1] = ffma2(xb.x, w1, acc[2][1]);
            acc[2][2] = ffma2(xb.x, w2, acc[2][2]);
            acc[2][3] = ffma2(xb.x, w3, acc[2][3]);
            acc[2][4] = ffma2(xb.x, w4, acc[2][4]);
            acc[2][5] = ffma2(xb.x, w5, acc[2][5]);
            acc[2][6] = ffma2(xb.x, w6, acc[2][6]);
            acc[2][7] = ffma2(xb.x, w7, acc[2][7]);
            acc[3][0] = ffma2(xb.y, w0, acc[3][0]);
            acc[3][1] = ffma2(xb.y, w1, acc[3][1]);
            acc[3][2] = ffma2(xb.y, w2, acc[3][2]);
            acc[3][3] = ffma2(xb.y, w3, acc[3][3]);
            acc[3][4] = ffma2(xb.y, w4, acc[3][4]);
            acc[3][5] = ffma2(xb.y, w5, acc[3][5]);
            acc[3][6] = ffma2(xb.y, w6, acc[3][6]);
            acc[3][7] = ffma2(xb.y, w7, acc[3][7]);
            x2a[0] = ffma2(xa.x, xa.x, x2a[0]);
            x2a[1] = ffma2(xa.y, xa.y, x2a[1]);
            x2a[2] = ffma2(xb.x, xb.x, x2a[2]);
            x2a[3] = ffma2(xb.y, xb.y, x2a[3]);
        }
        // store logits; rotate row order by kq to break the 4-way bank conflict
        #pragma unroll
        for (int jr = 0; jr < 8; ++jr) {
            const int j = (jr + 2 * kq) & 7;
            float* row = Lb + (k0 + j) * LS + nt;
            *(u64*)(row + 0) = acc[0][j];
            *(u64*)(row + 2) = acc[1][j];
            *(u64*)(row + 4) = acc[2][j];
            *(u64*)(row + 6) = acc[3][j];
        }
        if (kq == 0) {
            #pragma unroll
            for (int i = 0; i < 4; ++i) *(u64*)(x2s + nt + 2*i) = x2a[i];
        }
    }
    __syncthreads();

    // ---- Softmax per n = tid, write coefA + A (in place over Lb) ----
    {
        float x2 = x2s[tid];
        float lg[K_];
        float mx = -1e30f;
        #pragma unroll
        for (int k = 0; k < K_; ++k) {
            float4 cc = *(const float4*)(c4 + k * 4);
            float d = Lb[k * LS + tid];
            float l = fmaf(cc.y, d, fmaf(cc.x, x2, cc.z));
            lg[k] = l;
            mx = fmaxf(mx, l);
        }
        float s = 0.f;
        #pragma unroll
        for (int k = 0; k < K_; ++k) { float e = __expf(lg[k] - mx); lg[k] = e; s += e; }
        float inv = __fdividef(1.f, s);
        float* coefA = out + E_ELEMS + (size_t)b * K_ * N_ + n0 + tid;
        #pragma unroll
        for (int k = 0; k < K_; ++k) {
            float a = lg[k] * inv;
            coefA[(size_t)k * N_] = a;     // coalesced per k
            Lb[k * LS + tid] = a;          // same words this thread read -> safe
        }
    }
    __syncthreads();

    // ---- Phase 2: A^T X, 4k x 4c per thread, c interleaved (c = cg + 16*cj),
    //      n-split 2, LINEAR addressing (conflict-free: bank = 4*cg mod 32) ----
    {
        const int ns  = tid >> 7;            // 0..1 (128 n each)
        const int pos = tid & 127;
        const int kg  = pos >> 4;            // 0..7 -> k rows 4kg..4kg+3
        const int cg  = pos & 15;            // c cols: cg, cg+16, cg+32, cg+48
        const int k0b = kg * 4;
        const int nb  = ns * 128;

        const float* Ar = Lb + k0b * LS + nb;
        const float* Xc = Xs + cg  * XS + nb;

        u64 e[4][4];                         // [k][cj]
        u64 sa[4];
        #pragma unroll
        for (int j = 0; j < 4; ++j) {
            sa[j] = 0ull;
            #pragma unroll
            for (int cj = 0; cj < 4; ++cj) e[j][cj] = 0ull;
        }

        #pragma unroll 2
        for (int n = 0; n < 128; n += 4) {
            ulonglong2 x0 = *(const ulonglong2*)(Xc +  0 * XS + n);
            ulonglong2 x1 = *(const ulonglong2*)(Xc + 16 * XS + n);
            ulonglong2 x2v = *(const ulonglong2*)(Xc + 32 * XS + n);
            ulonglong2 x3 = *(const ulonglong2*)(Xc + 48 * XS + n);
            ulonglong2 a0 = *(const ulonglong2*)(Ar + 0 * LS + n);
            ulonglong2 a1 = *(const ulonglong2*)(Ar + 1 * LS + n);
            ulonglong2 a2 = *(const ulonglong2*)(Ar + 2 * LS + n);
            ulonglong2 a3 = *(const ulonglong2*)(Ar + 3 * LS + n);

            e[0][0] = ffma2(a0.x, x0.x,  e[0][0]); e[0][0] = ffma2(a0.y, x0.y,  e[0][0]);
            e[0][1] = ffma2(a0.x, x1.x,  e[0][1]); e[0][1] = ffma2(a0.y, x1.y,  e[0][1]);
            e[0][2] = ffma2(a0.x, x2v.x, e[0][2]); e[0][2] = ffma2(a0.y, x2v.y, e[0][2]);
            e[0][3] = ffma2(a0.x, x3.x,  e[0][3]); e[0][3] = ffma2(a0.y, x3.y,  e[0][3]);
            e[1][0] = ffma2(a1.x, x0.x,  e[1][0]); e[1][0] = ffma2(a1.y, x0.y,  e[1][0]);
            e[1][1] = ffma2(a1.x, x1.x,  e[1][1]); e[1][1] = ffma2(a1.y, x1.y,  e[1][1]);
            e[1][2] = ffma2(a1.x, x2v.x, e[1][2]); e[1][2] = ffma2(a1.y, x2v.y, e[1][2]);
            e[1][3] = ffma2(a1.x, x3.x,  e[1][3]); e[1][3] = ffma2(a1.y, x3.y,  e[1][3]);
            e[2][0] = ffma2(a2.x, x0.x,  e[2][0]); e[2][0] = ffma2(a2.y, x0.y,  e[2][0]);
            e[2][1] = ffma2(a2.x, x1.x,  e[2][1]); e[2][1] = ffma2(a2.y, x1.y,  e[2][1]);
            e[2][2] = ffma2(a2.x, x2v.x, e[2][2]); e[2][2] = ffma2(a2.y, x2v.y, e[2][2]);
            e[2][3] = ffma2(a2.x, x3.x,  e[2][3]); e[2][3] = ffma2(a2.y, x3.y,  e[2][3]);
            e[3][0] = ffma2(a3.x, x0.x,  e[3][0]); e[3][0] = ffma2(a3.y, x0.y,  e[3][0]);
            e[3][1] = ffma2(a3.x, x1.x,  e[3][1]); e[3][1] = ffma2(a3.y, x1.y,  e[3][1]);
            e[3][2] = ffma2(a3.x, x2v.x, e[3][2]); e[3][2] = ffma2(a3.y, x2v.y, e[3][2]);
            e[3][3] = ffma2(a3.x, x3.x,  e[3][3]); e[3][3] = ffma2(a3.y, x3.y,  e[3][3]);
            sa[0] = fadd2(sa[0], fadd2(a0.x, a0.y));
            sa[1] = fadd2(sa[1], fadd2(a1.x, a1.y));
            sa[2] = fadd2(sa[2], fadd2(a2.x, a2.y));
            sa[3] = fadd2(sa[3], fadd2(a3.x, a3.y));
        }

        float* E = out + b * (K_ * C_);
        #pragma unroll
        for (int j = 0; j < 4; ++j) {
            #pragma unroll
            for (int cj = 0; cj < 4; ++cj) {
                float2 f = unpack2(e[j][cj]);
                atomicAdd(&E[(k0b + j) * C_ + cg + 16 * cj], f.x + f.y);
            }
        }
        if (cg == 0) {
            #pragma unroll
            for (int j = 0; j < 4; ++j) {
                float2 f = unpack2(sa[j]);
                atomicAdd(&g_asum[b*K_ + k0b + j], f.x + f.y);
            }
        }
    }
}

// ---------------------------------------------------------------------------
__global__ void enc_final(const float* __restrict__ cwg, float* __restrict__ out) {
    int i = blockIdx.x * 256 + threadIdx.x;
    if (i >= E_ELEMS) return;
    int c  = i & 63;
    int bk = i >> 6;
    int k  = bk & 31;
    out[i] -= g_asum[bk] * cwg[k*64 + c];
}

// ---------------------------------------------------------------------------
extern "C" void kernel_launch(void* const* d_in, const int* in_sizes, int n_in,
                              void* d_out, int out_size) {
    const float* X   = (const float*)d_in[0];
    const float* cwg = (const float*)d_in[1];
    const float* scl = (const float*)d_in[2];
    float* out = (float*)d_out;

    const int smem_bytes = (64*XS + 32*LS + 64*CWS + 256 + 32 + 128) * 4; // 110,592 B
    cudaFuncSetAttribute(enc_main, cudaFuncAttributeMaxDynamicSharedMemorySize,
                         smem_bytes);

    enc_init<<<32, 256>>>(out);
    enc_main<<<2048, 256, smem_bytes>>>(X, cwg, scl, out);
    enc_final<<<32, 256>>>(cwg, out);
}

// round 12
// speedup vs baseline: 1.1736x; 1.1736x over previous
#include <cuda_runtime.h>

#define B_  4
#define C_  64
#define K_  32
#define N_  131072           // D*H*W
#define TN  128              // n-tile per block
#define XS  132              // X tile row stride (words; 528B = 16B-aligned)
#define LS  132              // L/A tile row stride
#define CWS 36               // transposed codeword stride
#define E_ELEMS (B_*K_*C_)   // 8192

__device__ float g_asum[B_*K_];

typedef unsigned long long u64;

__device__ __forceinline__ u64 ffma2(u64 a, u64 b, u64 c) {
    u64 d; asm("fma.rn.f32x2 %0, %1, %2, %3;" : "=l"(d) : "l"(a), "l"(b), "l"(c));
    return d;
}
__device__ __forceinline__ u64 fadd2(u64 a, u64 b) {
    u64 d; asm("add.rn.f32x2 %0, %1, %2;" : "=l"(d) : "l"(a), "l"(b));
    return d;
}
__device__ __forceinline__ u64 pack2(float lo, float hi) {
    u64 d; asm("mov.b64 %0, {%1, %2};" : "=l"(d) : "f"(lo), "f"(hi));
    return d;
}
__device__ __forceinline__ float2 unpack2(u64 v) {
    float2 r; asm("mov.b64 {%0, %1}, %2;" : "=f"(r.x), "=f"(r.y) : "l"(v));
    return r;
}

// ---------------------------------------------------------------------------
__global__ void enc_init(float* __restrict__ out) {
    int i = blockIdx.x * 256 + threadIdx.x;
    if (i < E_ELEMS) out[i] = 0.0f;
    if (i < B_*K_)   g_asum[i] = 0.0f;
}

// ---------------------------------------------------------------------------
// One block = one (b, 128-n) tile. Grid = 4 * 1024 = 4096 blocks, 128 threads.
// ---------------------------------------------------------------------------
__global__ __launch_bounds__(128, 3) void enc_main(
    const float* __restrict__ X,    // (B, C, N)
    const float* __restrict__ cwg,  // (K, C)
    const float* __restrict__ sclg, // (K,)
    float* __restrict__ out)        // [E | coefA]
{
    extern __shared__ float sm[];
    float* Xs  = sm;                  // 64*132  X tile, [c][n] linear
    float* Lb  = Xs + 64*XS;          // 32*132  logits -> A, [k][n] linear
    float* cwt = Lb + 32*LS;          // 64*36   codewords^T
    float* x2s = cwt + 64*CWS;        // 128
    float* scl = x2s + 128;           // 32
    float* c4  = scl + 32;            // 32*4  (scl, -2*scl, scl*c2, 0)

    const int tid = threadIdx.x;
    const int b   = blockIdx.x >> 10;          // /1024
    const int n0  = (blockIdx.x & 1023) << 7;  // *128

    // ---- stage X tile (vectorized, coalesced, linear layout) ----
    const float* Xb = X + (size_t)b * C_ * N_ + n0;
    #pragma unroll
    for (int i = 0; i < 16; ++i) {
        int f = i * 128 + tid;
        int c = f >> 5, q = f & 31;            // 32 float4 per 128-n row
        float4 v = *(const float4*)(Xb + (size_t)c * N_ + q * 4);
        *(float4*)(Xs + c * XS + q * 4) = v;
    }
    // ---- stage codewords transposed [c][k] ----
    #pragma unroll
    for (int i = 0; i < 16; ++i) {
        int f = i * 128 + tid;        // f = k*64 + c
        cwt[(f & 63) * CWS + (f >> 6)] = cwg[f];
    }
    if (tid < K_) scl[tid] = sclg[tid];
    __syncthreads();

    if (tid < K_) {
        float s = 0.f;
        #pragma unroll
        for (int c = 0; c < C_; ++c) { float w = cwt[c*CWS + tid]; s = fmaf(w, w, s); }
        float sc = scl[tid];
        float4 v; v.x = sc; v.y = -2.f * sc; v.z = sc * s; v.w = 0.f;
        *(float4*)(c4 + tid * 4) = v;
    }

    // ---- Phase 1: logits GEMM (dots only), 4k x 8n per thread, n-paired ----
    const int k0 = (tid & 7) * 4;
    const int nt = (tid >> 3) * 8;    // 0..120
    u64 acc[4][4];                    // [npair][k]
    u64 x2a[4];
    #pragma unroll
    for (int i = 0; i < 4; ++i) {
        x2a[i] = 0ull;
        #pragma unroll
        for (int j = 0; j < 4; ++j) acc[i][j] = 0ull;
    }

    #pragma unroll 8
    for (int c = 0; c < 64; ++c) {
        ulonglong2 xa = *(const ulonglong2*)(Xs + c * XS + nt);
        ulonglong2 xb = *(const ulonglong2*)(Xs + c * XS + nt + 4);
        float4 w = *(const float4*)(cwt + c * CWS + k0);
        u64 w0 = pack2(w.x, w.x), w1 = pack2(w.y, w.y);
        u64 w2 = pack2(w.z, w.z), w3 = pack2(w.w, w.w);
        acc[0][0] = ffma2(xa.x, w0, acc[0][0]);
        acc[0][1] = ffma2(xa.x, w1, acc[0][1]);
        acc[0][2] = ffma2(xa.x, w2, acc[0][2]);
        acc[0][3] = ffma2(xa.x, w3, acc[0][3]);
        acc[1][0] = ffma2(xa.y, w0, acc[1][0]);
        acc[1][1] = ffma2(xa.y, w1, acc[1][1]);
        acc[1][2] = ffma2(xa.y, w2, acc[1][2]);
        acc[1][3] = ffma2(xa.y, w3, acc[1][3]);
        acc[2][0] = ffma2(xb.x, w0, acc[2][0]);
        acc[2][1] = ffma2(xb.x, w1, acc[2][1]);
        acc[2][2] = ffma2(xb.x, w2, acc[2][2]);
        acc[2][3] = ffma2(xb.x, w3, acc[2][3]);
        acc[3][0] = ffma2(xb.y, w0, acc[3][0]);
        acc[3][1] = ffma2(xb.y, w1, acc[3][1]);
        acc[3][2] = ffma2(xb.y, w2, acc[3][2]);
        acc[3][3] = ffma2(xb.y, w3, acc[3][3]);
        x2a[0] = ffma2(xa.x, xa.x, x2a[0]);
        x2a[1] = ffma2(xa.y, xa.y, x2a[1]);
        x2a[2] = ffma2(xb.x, xb.x, x2a[2]);
        x2a[3] = ffma2(xb.y, xb.y, x2a[3]);
    }
    #pragma unroll
    for (int j = 0; j < 4; ++j)
        #pragma unroll
        for (int i = 0; i < 4; ++i)
            *(u64*)(Lb + (k0 + j) * LS + nt + 2*i) = acc[i][j];
    if ((tid & 7) == 0) {
        #pragma unroll
        for (int i = 0; i < 4; ++i) *(u64*)(x2s + nt + 2*i) = x2a[i];
    }
    __syncthreads();

    // ---- Softmax per n = tid (0..127), write coefA + A (in place) ----
    {
        float x2 = x2s[tid];
        float lg[K_];
        float mx = -1e30f;
        #pragma unroll
        for (int k = 0; k < K_; ++k) {
            float4 cc = *(const float4*)(c4 + k * 4);
            float d = Lb[k * LS + tid];
            float l = fmaf(cc.y, d, fmaf(cc.x, x2, cc.z));
            lg[k] = l;
            mx = fmaxf(mx, l);
        }
        float s = 0.f;
        #pragma unroll
        for (int k = 0; k < K_; ++k) { float e = __expf(lg[k] - mx); lg[k] = e; s += e; }
        float inv = __fdividef(1.f, s);
        float* coefA = out + E_ELEMS + (size_t)b * K_ * N_ + n0 + tid;
        #pragma unroll
        for (int k = 0; k < K_; ++k) {
            float a = lg[k] * inv;
            coefA[(size_t)k * N_] = a;     // coalesced per k
            Lb[k * LS + tid] = a;          // same words this thread read -> safe
        }
    }
    __syncthreads();

    // ---- Phase 2: A^T X, 4k x 4c per thread, c interleaved (c = cg + 16*cj),
    //      128 n, LINEAR addressing (bank = 4*cg mod 32, conflict-free) ----
    {
        const int kg  = tid >> 4;            // 0..7 -> k rows 4kg..4kg+3
        const int cg  = tid & 15;            // c cols: cg, cg+16, cg+32, cg+48
        const int k0b = kg * 4;

        const float* Ar = Lb + k0b * LS;
        const float* Xc = Xs + cg  * XS;

        u64 e[4][4];                         // [k][cj]
        u64 sa[4];
        #pragma unroll
        for (int j = 0; j < 4; ++j) {
            sa[j] = 0ull;
            #pragma unroll
            for (int cj = 0; cj < 4; ++cj) e[j][cj] = 0ull;
        }

        #pragma unroll 2
        for (int n = 0; n < TN; n += 4) {
            ulonglong2 x0 = *(const ulonglong2*)(Xc +  0 * XS + n);
            ulonglong2 x1 = *(const ulonglong2*)(Xc + 16 * XS + n);
            ulonglong2 x2v = *(const ulonglong2*)(Xc + 32 * XS + n);
            ulonglong2 x3 = *(const ulonglong2*)(Xc + 48 * XS + n);
            ulonglong2 a0 = *(const ulonglong2*)(Ar + 0 * LS + n);
            ulonglong2 a1 = *(const ulonglong2*)(Ar + 1 * LS + n);
            ulonglong2 a2 = *(const ulonglong2*)(Ar + 2 * LS + n);
            ulonglong2 a3 = *(const ulonglong2*)(Ar + 3 * LS + n);

            e[0][0] = ffma2(a0.x, x0.x,  e[0][0]); e[0][0] = ffma2(a0.y, x0.y,  e[0][0]);
            e[0][1] = ffma2(a0.x, x1.x,  e[0][1]); e[0][1] = ffma2(a0.y, x1.y,  e[0][1]);
            e[0][2] = ffma2(a0.x, x2v.x, e[0][2]); e[0][2] = ffma2(a0.y, x2v.y, e[0][2]);
            e[0][3] = ffma2(a0.x, x3.x,  e[0][3]); e[0][3] = ffma2(a0.y, x3.y,  e[0][3]);
            e[1][0] = ffma2(a1.x, x0.x,  e[1][0]); e[1][0] = ffma2(a1.y, x0.y,  e[1][0]);
            e[1][1] = ffma2(a1.x, x1.x,  e[1][1]); e[1][1] = ffma2(a1.y, x1.y,  e[1][1]);
            e[1][2] = ffma2(a1.x, x2v.x, e[1][2]); e[1][2] = ffma2(a1.y, x2v.y, e[1][2]);
            e[1][3] = ffma2(a1.x, x3.x,  e[1][3]); e[1][3] = ffma2(a1.y, x3.y,  e[1][3]);
            e[2][0] = ffma2(a2.x, x0.x,  e[2][0]); e[2][0] = ffma2(a2.y, x0.y,  e[2][0]);
            e[2][1] = ffma2(a2.x, x1.x,  e[2][1]); e[2][1] = ffma2(a2.y, x1.y,  e[2][1]);
            e[2][2] = ffma2(a2.x, x2v.x, e[2][2]); e[2][2] = ffma2(a2.y, x2v.y, e[2][2]);
            e[2][3] = ffma2(a2.x, x3.x,  e[2][3]); e[2][3] = ffma2(a2.y, x3.y,  e[2][3]);
            e[3][0] = ffma2(a3.x, x0.x,  e[3][0]); e[3][0] = ffma2(a3.y, x0.y,  e[3][0]);
            e[3][1] = ffma2(a3.x, x1.x,  e[3][1]); e[3][1] = ffma2(a3.y, x1.y,  e[3][1]);
            e[3][2] = ffma2(a3.x, x2v.x, e[3][2]); e[3][2] = ffma2(a3.y, x2v.y, e[3][2]);
            e[3][3] = ffma2(a3.x, x3.x,  e[3][3]); e[3][3] = ffma2(a3.y, x3.y,  e[3][3]);
            sa[0] = fadd2(sa[0], fadd2(a0.x, a0.y));
            sa[1] = fadd2(sa[1], fadd2(a1.x, a1.y));
            sa[2] = fadd2(sa[2], fadd2(a2.x, a2.y));
            sa[3] = fadd2(sa[3], fadd2(a3.x, a3.y));
        }

        float* E = out + b * (K_ * C_);
        #pragma unroll
        for (int j = 0; j < 4; ++j) {
            #pragma unroll
            for (int cj = 0; cj < 4; ++cj) {
                float2 f = unpack2(e[j][cj]);
                atomicAdd(&E[(k0b + j) * C_ + cg + 16 * cj], f.x + f.y);
            }
        }
        if (cg == 0) {
            #pragma unroll
            for (int j = 0; j < 4; ++j) {
                float2 f = unpack2(sa[j]);
                atomicAdd(&g_asum[b*K_ + k0b + j], f.x + f.y);
            }
        }
    }
}

// ---------------------------------------------------------------------------
__global__ void enc_final(const float* __restrict__ cwg, float* __restrict__ out) {
    int i = blockIdx.x * 256 + threadIdx.x;
    if (i >= E_ELEMS) return;
    int c  = i & 63;
    int bk = i >> 6;
    int k  = bk & 31;
    out[i] -= g_asum[bk] * cwg[k*64 + c];
}

// ---------------------------------------------------------------------------
extern "C" void kernel_launch(void* const* d_in, const int* in_sizes, int n_in,
                              void* d_out, int out_size) {
    const float* X   = (const float*)d_in[0];
    const float* cwg = (const float*)d_in[1];
    const float* scl = (const float*)d_in[2];
    float* out = (float*)d_out;

    const int smem_bytes = (64*XS + 32*LS + 64*CWS + 128 + 32 + 128) * 4; // 61,056 B
    cudaFuncSetAttribute(enc_main, cudaFuncAttributeMaxDynamicSharedMemorySize,
                         smem_bytes);

    enc_init<<<32, 256>>>(out);
    enc_main<<<4096, 128, smem_bytes>>>(X, cwg, scl, out);
    enc_final<<<32, 256>>>(cwg, out);
}